// round 2
// baseline (speedup 1.0000x reference)
#include <cuda_runtime.h>
#include <math.h>

#define D_MODEL 512
#define NHEAD   8
#define DK      64
#define BB      4
#define NN      2048
#define M_TOTAL (BB * NN)     // 8192
#define BH      (BB * NHEAD)  // 32

// Scratch (allocation-free: static __device__ arrays)
__device__ float g_q[BH * NN * DK];        // [bh][n][dk]
__device__ float g_k[BH * NN * DK];
__device__ float g_v[BH * NN * DK];
__device__ float g_attn[M_TOTAL * D_MODEL]; // [b*n][512] (heads re-merged)

// ---------------------------------------------------------------------------
// GEMM: out = X[M,512] @ W[512,512] + bias.  64x64 tile, BK=16, 256 threads,
// 4x4 microtile per thread. split_heads!=0 -> write [bh][n][dk] layout.
// ---------------------------------------------------------------------------
__global__ void __launch_bounds__(256)
gemm_kernel(const float* __restrict__ X, const float* __restrict__ W,
            const float* __restrict__ bias, float* __restrict__ out,
            int split_heads)
{
    __shared__ float As[16][68];   // [k][m] (transposed)
    __shared__ float Bs[16][68];   // [k][n]

    const int tid = threadIdx.x;
    const int tx  = tid & 15;
    const int ty  = tid >> 4;
    const int m0  = blockIdx.y * 64;
    const int n0  = blockIdx.x * 64;

    const int lm  = tid >> 2;   // 0..63 : A row
    const int lq  = tid & 3;    // 0..3  : A quad (k)
    const int lk  = tid >> 4;   // 0..15 : B row (k)
    const int ln4 = tid & 15;   // 0..15 : B col quad

    float acc[4][4] = {};

    for (int kt = 0; kt < 512; kt += 16) {
        float4 a4 = *reinterpret_cast<const float4*>(&X[(size_t)(m0 + lm) * 512 + kt + lq * 4]);
        As[lq * 4 + 0][lm] = a4.x;
        As[lq * 4 + 1][lm] = a4.y;
        As[lq * 4 + 2][lm] = a4.z;
        As[lq * 4 + 3][lm] = a4.w;
        float4 b4 = *reinterpret_cast<const float4*>(&W[(size_t)(kt + lk) * 512 + n0 + ln4 * 4]);
        *reinterpret_cast<float4*>(&Bs[lk][ln4 * 4]) = b4;
        __syncthreads();

        #pragma unroll
        for (int kk = 0; kk < 16; kk++) {
            float4 av = *reinterpret_cast<const float4*>(&As[kk][ty * 4]);
            float4 bv = *reinterpret_cast<const float4*>(&Bs[kk][tx * 4]);
            float a[4] = {av.x, av.y, av.z, av.w};
            float b[4] = {bv.x, bv.y, bv.z, bv.w};
            #pragma unroll
            for (int i = 0; i < 4; i++)
                #pragma unroll
                for (int j = 0; j < 4; j++)
                    acc[i][j] += a[i] * b[j];
        }
        __syncthreads();
    }

    // epilogue
    if (split_heads) {
        // col = n0 + tx*4 + j ; since n0 % 64 == 0 and tx*4+j < 64:
        const int h  = n0 >> 6;
        const int d0 = tx * 4;
        #pragma unroll
        for (int i = 0; i < 4; i++) {
            int row = m0 + ty * 4 + i;
            int b_  = row >> 11;
            int n_  = row & 2047;
            float4 v;
            v.x = acc[i][0] + bias[n0 + d0 + 0];
            v.y = acc[i][1] + bias[n0 + d0 + 1];
            v.z = acc[i][2] + bias[n0 + d0 + 2];
            v.w = acc[i][3] + bias[n0 + d0 + 3];
            size_t off = ((size_t)(b_ * NHEAD + h) * NN + n_) * DK + d0;
            *reinterpret_cast<float4*>(&out[off]) = v;
        }
    } else {
        #pragma unroll
        for (int i = 0; i < 4; i++) {
            int row = m0 + ty * 4 + i;
            float4 v;
            v.x = acc[i][0] + bias[n0 + tx * 4 + 0];
            v.y = acc[i][1] + bias[n0 + tx * 4 + 1];
            v.z = acc[i][2] + bias[n0 + tx * 4 + 2];
            v.w = acc[i][3] + bias[n0 + tx * 4 + 3];
            *reinterpret_cast<float4*>(&out[(size_t)row * 512 + n0 + tx * 4]) = v;
        }
    }
}

// ---------------------------------------------------------------------------
// Flash attention: per (bh, 64-query block). BM=BN=64, d=64, 256 threads,
// 4x4 microtile per thread. Online softmax in base-2 (scale folded into Q).
// ---------------------------------------------------------------------------
__global__ void __launch_bounds__(256)
attn_kernel()
{
    __shared__ float Qs[64][64];   // [d][r]   (Q transposed, pre-scaled)
    __shared__ float KPs[64][64];  // first Ks [d][c]; then Pts [c][r]
    __shared__ float Vs[64][64];   // [c][d]

    const int tid = threadIdx.x;
    const int tx  = tid & 15;
    const int ty  = tid >> 4;
    const int bh  = blockIdx.y;
    const int m0  = blockIdx.x * 64;

    const float* Qb = g_q + (size_t)bh * NN * DK;
    const float* Kb = g_k + (size_t)bh * NN * DK;
    const float* Vb = g_v + (size_t)bh * NN * DK;

    const int lr = tid >> 2;  // 0..63 row
    const int lq = tid & 3;   // 0..3

    // scale = 1/sqrt(64) * log2(e), folded into Q
    const float sc = 0.125f * 1.4426950408889634f;

    // load Q transposed, pre-scaled
    #pragma unroll
    for (int t = 0; t < 4; t++) {
        float4 v = *reinterpret_cast<const float4*>(&Qb[(size_t)(m0 + lr) * DK + lq * 16 + t * 4]);
        Qs[lq * 16 + t * 4 + 0][lr] = v.x * sc;
        Qs[lq * 16 + t * 4 + 1][lr] = v.y * sc;
        Qs[lq * 16 + t * 4 + 2][lr] = v.z * sc;
        Qs[lq * 16 + t * 4 + 3][lr] = v.w * sc;
    }

    float o[4][4] = {};
    float mI[4], lI[4];
    #pragma unroll
    for (int i = 0; i < 4; i++) { mI[i] = -1e30f; lI[i] = 0.0f; }

    for (int kb = 0; kb < NN; kb += 64) {
        __syncthreads();  // prev iter's Pts/Vs reads done; Qs store visible (1st iter)

        // load K transposed, V direct
        #pragma unroll
        for (int t = 0; t < 4; t++) {
            float4 kv = *reinterpret_cast<const float4*>(&Kb[(size_t)(kb + lr) * DK + lq * 16 + t * 4]);
            KPs[lq * 16 + t * 4 + 0][lr] = kv.x;
            KPs[lq * 16 + t * 4 + 1][lr] = kv.y;
            KPs[lq * 16 + t * 4 + 2][lr] = kv.z;
            KPs[lq * 16 + t * 4 + 3][lr] = kv.w;
            float4 vv = *reinterpret_cast<const float4*>(&Vb[(size_t)(kb + lr) * DK + lq * 16 + t * 4]);
            *reinterpret_cast<float4*>(&Vs[lr][lq * 16 + t * 4]) = vv;
        }
        __syncthreads();

        // S = (Q*sc) @ K^T   (base-2-ready)
        float s[4][4] = {};
        #pragma unroll 16
        for (int d = 0; d < 64; d++) {
            float4 q4 = *reinterpret_cast<const float4*>(&Qs[d][ty * 4]);
            float4 k4 = *reinterpret_cast<const float4*>(&KPs[d][tx * 4]);
            float qa[4] = {q4.x, q4.y, q4.z, q4.w};
            float ka[4] = {k4.x, k4.y, k4.z, k4.w};
            #pragma unroll
            for (int i = 0; i < 4; i++)
                #pragma unroll
                for (int j = 0; j < 4; j++)
                    s[i][j] += qa[i] * ka[j];
        }

        // online softmax stats (row groups = 16 lanes sharing ty)
        float corr[4];
        #pragma unroll
        for (int i = 0; i < 4; i++) {
            float mx = fmaxf(fmaxf(s[i][0], s[i][1]), fmaxf(s[i][2], s[i][3]));
            #pragma unroll
            for (int off = 8; off >= 1; off >>= 1)
                mx = fmaxf(mx, __shfl_xor_sync(0xffffffffu, mx, off));
            float mNew = fmaxf(mI[i], mx);
            corr[i] = exp2f(mI[i] - mNew);
            float rs = 0.0f;
            #pragma unroll
            for (int j = 0; j < 4; j++) {
                float p = exp2f(s[i][j] - mNew);
                s[i][j] = p;
                rs += p;
            }
            #pragma unroll
            for (int off = 8; off >= 1; off >>= 1)
                rs += __shfl_xor_sync(0xffffffffu, rs, off);
            lI[i] = lI[i] * corr[i] + rs;
            mI[i] = mNew;
            #pragma unroll
            for (int j = 0; j < 4; j++)
                o[i][j] *= corr[i];
        }

        __syncthreads();  // all Ks reads done -> reuse buffer as Pts

        // write P transposed: Pts[c][r]
        #pragma unroll
        for (int j = 0; j < 4; j++) {
            float4 pv;
            pv.x = s[0][j]; pv.y = s[1][j]; pv.z = s[2][j]; pv.w = s[3][j];
            *reinterpret_cast<float4*>(&KPs[tx * 4 + j][ty * 4]) = pv;
        }
        __syncthreads();

        // O += P @ V
        #pragma unroll 16
        for (int k = 0; k < 64; k++) {
            float4 p4 = *reinterpret_cast<const float4*>(&KPs[k][ty * 4]);
            float4 v4 = *reinterpret_cast<const float4*>(&Vs[k][tx * 4]);
            float pa[4] = {p4.x, p4.y, p4.z, p4.w};
            float va[4] = {v4.x, v4.y, v4.z, v4.w};
            #pragma unroll
            for (int i = 0; i < 4; i++)
                #pragma unroll
                for (int j = 0; j < 4; j++)
                    o[i][j] += pa[i] * va[j];
        }
    }

    // epilogue: merge heads -> g_attn[b*n][h*64+d]
    const int b_ = bh >> 3;
    const int h  = bh & 7;
    #pragma unroll
    for (int i = 0; i < 4; i++) {
        float inv = 1.0f / lI[i];
        int m = m0 + ty * 4 + i;
        float4 ov;
        ov.x = o[i][0] * inv;
        ov.y = o[i][1] * inv;
        ov.z = o[i][2] * inv;
        ov.w = o[i][3] * inv;
        size_t off = ((size_t)(b_ * NN + m)) * D_MODEL + h * DK + tx * 4;
        *reinterpret_cast<float4*>(&g_attn[off]) = ov;
    }
}

// ---------------------------------------------------------------------------
extern "C" void kernel_launch(void* const* d_in, const int* in_sizes, int n_in,
                              void* d_out, int out_size)
{
    (void)in_sizes; (void)n_in; (void)out_size;
    const float* x  = (const float*)d_in[0];
    const float* Wq = (const float*)d_in[1];
    const float* bq = (const float*)d_in[2];
    const float* Wk = (const float*)d_in[3];
    const float* bk = (const float*)d_in[4];
    const float* Wv = (const float*)d_in[5];
    const float* bv = (const float*)d_in[6];
    const float* Wo = (const float*)d_in[7];
    const float* bo = (const float*)d_in[8];

    float *qp, *kp, *vp, *ap;
    cudaGetSymbolAddress((void**)&qp, g_q);
    cudaGetSymbolAddress((void**)&kp, g_k);
    cudaGetSymbolAddress((void**)&vp, g_v);
    cudaGetSymbolAddress((void**)&ap, g_attn);

    dim3 gemm_grid(D_MODEL / 64, M_TOTAL / 64);   // (8, 128)
    gemm_kernel<<<gemm_grid, 256>>>(x, Wq, bq, qp, 1);
    gemm_kernel<<<gemm_grid, 256>>>(x, Wk, bk, kp, 1);
    gemm_kernel<<<gemm_grid, 256>>>(x, Wv, bv, vp, 1);

    dim3 attn_grid(NN / 64, BH);                  // (32, 32)
    attn_kernel<<<attn_grid, 256>>>();

    gemm_kernel<<<gemm_grid, 256>>>(ap, Wo, bo, (float*)d_out, 0);
}

// round 3
// speedup vs baseline: 2.0353x; 2.0353x over previous
#include <cuda_runtime.h>
#include <cuda_bf16.h>
#include <mma.h>
#include <math.h>
#include <stdint.h>

using namespace nvcuda;

#define D_MODEL 512
#define NHEAD   8
#define DK      64
#define BB      4
#define NN      2048
#define M_TOTAL (BB * NN)     // 8192
#define BH      (BB * NHEAD)  // 32

// Scratch (allocation-free: static __device__ arrays)
__device__ float g_q[BH * NN * DK];        // [bh][n][dk]
__device__ float g_k[BH * NN * DK];
__device__ float g_v[BH * NN * DK];
__device__ float g_attn[M_TOTAL * D_MODEL]; // [b*n][512] (heads re-merged)

// ---------------------------------------------------------------------------
// helpers
// ---------------------------------------------------------------------------
__device__ __forceinline__ uint32_t packb(float x, float y) {
    __nv_bfloat162 t = __floats2bfloat162_rn(x, y);
    return *reinterpret_cast<uint32_t*>(&t);
}

// hi/lo bf16 split of a float pair, packed into two b32 regs
__device__ __forceinline__ void split2(float x, float y, uint32_t& hi, uint32_t& lo) {
    float hx = __bfloat162float(__float2bfloat16(x));
    float hy = __bfloat162float(__float2bfloat16(y));
    hi = packb(hx, hy);
    lo = packb(x - hx, y - hy);
}

__device__ __forceinline__ void mma16816(float* c, const uint32_t* a, uint32_t b0, uint32_t b1) {
    asm volatile(
        "mma.sync.aligned.m16n8k16.row.col.f32.bf16.bf16.f32 "
        "{%0,%1,%2,%3}, {%4,%5,%6,%7}, {%8,%9}, {%0,%1,%2,%3};\n"
        : "+f"(c[0]), "+f"(c[1]), "+f"(c[2]), "+f"(c[3])
        : "r"(a[0]), "r"(a[1]), "r"(a[2]), "r"(a[3]), "r"(b0), "r"(b1));
}

// ---------------------------------------------------------------------------
// GEMM (tensor core, split bf16): out = X[M,512] @ W[512,512] + bias
// 128x64 block tile, BK=32, 256 threads = 8 warps (4x2), warp tile 32x32.
// ---------------------------------------------------------------------------
#define XS_LD 40   // 32 + 8 pad (bf16 elems)
#define WS_LD 72   // 64 + 8 pad
#define CS_LD 68   // 64 + 4 pad (f32)

__global__ void __launch_bounds__(256)
gemm_tc(const float* __restrict__ X, const float* __restrict__ W,
        const float* __restrict__ bias, float* __restrict__ out,
        int split_heads)
{
    // union: bf16 tiles (29696 B) then f32 stage (34816 B)
    __shared__ __align__(16) unsigned char smem_raw[128 * CS_LD * 4];
    __nv_bfloat16* Xhi = (__nv_bfloat16*)smem_raw;            // [128][XS_LD]
    __nv_bfloat16* Xlo = Xhi + 128 * XS_LD;
    __nv_bfloat16* Whi = Xlo + 128 * XS_LD;                   // [32][WS_LD]
    __nv_bfloat16* Wlo = Whi + 32 * WS_LD;
    float* Cst = (float*)smem_raw;                            // [128][CS_LD]

    const int tid = threadIdx.x;
    const int wid = tid >> 5;
    const int wm  = wid & 3;       // 0..3 -> 32-row slab
    const int wn  = wid >> 2;      // 0..1 -> 32-col slab
    const int m0  = blockIdx.y * 128;
    const int n0  = blockIdx.x * 64;

    wmma::fragment<wmma::accumulator, 16, 16, 16, float> acc[2][2];
    #pragma unroll
    for (int i = 0; i < 2; i++)
        #pragma unroll
        for (int j = 0; j < 2; j++)
            wmma::fill_fragment(acc[i][j], 0.0f);

    const int xrow = tid >> 3;           // 0..31
    const int xcol = (tid & 7) * 4;      // 0..28
    const int wrow = tid >> 4;           // 0..15
    const int wcol = (tid & 15) * 4;     // 0..60

    for (int kt = 0; kt < 512; kt += 32) {
        // load X tile 128x32 (4 passes of 32 rows)
        #pragma unroll
        for (int t = 0; t < 4; t++) {
            int r = xrow + t * 32;
            float4 v = *reinterpret_cast<const float4*>(&X[(size_t)(m0 + r) * 512 + kt + xcol]);
            uint32_t h01, l01, h23, l23;
            split2(v.x, v.y, h01, l01);
            split2(v.z, v.w, h23, l23);
            *reinterpret_cast<uint32_t*>(&Xhi[r * XS_LD + xcol])     = h01;
            *reinterpret_cast<uint32_t*>(&Xhi[r * XS_LD + xcol + 2]) = h23;
            *reinterpret_cast<uint32_t*>(&Xlo[r * XS_LD + xcol])     = l01;
            *reinterpret_cast<uint32_t*>(&Xlo[r * XS_LD + xcol + 2]) = l23;
        }
        // load W tile 32x64 (2 passes of 16 rows)
        #pragma unroll
        for (int t = 0; t < 2; t++) {
            int r = wrow + t * 16;
            float4 v = *reinterpret_cast<const float4*>(&W[(size_t)(kt + r) * 512 + n0 + wcol]);
            uint32_t h01, l01, h23, l23;
            split2(v.x, v.y, h01, l01);
            split2(v.z, v.w, h23, l23);
            *reinterpret_cast<uint32_t*>(&Whi[r * WS_LD + wcol])     = h01;
            *reinterpret_cast<uint32_t*>(&Whi[r * WS_LD + wcol + 2]) = h23;
            *reinterpret_cast<uint32_t*>(&Wlo[r * WS_LD + wcol])     = l01;
            *reinterpret_cast<uint32_t*>(&Wlo[r * WS_LD + wcol + 2]) = l23;
        }
        __syncthreads();

        #pragma unroll
        for (int kk = 0; kk < 32; kk += 16) {
            wmma::fragment<wmma::matrix_a, 16, 16, 16, __nv_bfloat16, wmma::row_major> ahi[2], alo[2];
            #pragma unroll
            for (int i = 0; i < 2; i++) {
                wmma::load_matrix_sync(ahi[i], Xhi + (wm * 32 + 16 * i) * XS_LD + kk, XS_LD);
                wmma::load_matrix_sync(alo[i], Xlo + (wm * 32 + 16 * i) * XS_LD + kk, XS_LD);
            }
            #pragma unroll
            for (int j = 0; j < 2; j++) {
                wmma::fragment<wmma::matrix_b, 16, 16, 16, __nv_bfloat16, wmma::row_major> bhi, blo;
                wmma::load_matrix_sync(bhi, Whi + kk * WS_LD + wn * 32 + 16 * j, WS_LD);
                wmma::load_matrix_sync(blo, Wlo + kk * WS_LD + wn * 32 + 16 * j, WS_LD);
                #pragma unroll
                for (int i = 0; i < 2; i++) {
                    wmma::mma_sync(acc[i][j], ahi[i], bhi, acc[i][j]);
                    wmma::mma_sync(acc[i][j], ahi[i], blo, acc[i][j]);
                    wmma::mma_sync(acc[i][j], alo[i], bhi, acc[i][j]);
                }
            }
        }
        __syncthreads();
    }

    // stage accumulators to smem
    #pragma unroll
    for (int i = 0; i < 2; i++)
        #pragma unroll
        for (int j = 0; j < 2; j++)
            wmma::store_matrix_sync(Cst + (wm * 32 + 16 * i) * CS_LD + wn * 32 + 16 * j,
                                    acc[i][j], CS_LD, wmma::mem_row_major);
    __syncthreads();

    // epilogue: add bias, write out
    const int orow = tid >> 4;          // 0..15
    const int ocol = (tid & 15) * 4;    // 0..60
    float4 b4 = *reinterpret_cast<const float4*>(&bias[n0 + ocol]);
    if (split_heads) {
        const int h = blockIdx.x;       // n0 = h*64
        #pragma unroll
        for (int t = 0; t < 8; t++) {
            int r = orow + t * 16;
            int rg = m0 + r;
            int b_ = rg >> 11;
            int n_ = rg & 2047;
            float4 v = *reinterpret_cast<const float4*>(&Cst[r * CS_LD + ocol]);
            v.x += b4.x; v.y += b4.y; v.z += b4.z; v.w += b4.w;
            size_t off = ((size_t)(b_ * NHEAD + h) * NN + n_) * DK + ocol;
            *reinterpret_cast<float4*>(&out[off]) = v;
        }
    } else {
        #pragma unroll
        for (int t = 0; t < 8; t++) {
            int r = orow + t * 16;
            int rg = m0 + r;
            float4 v = *reinterpret_cast<const float4*>(&Cst[r * CS_LD + ocol]);
            v.x += b4.x; v.y += b4.y; v.z += b4.z; v.w += b4.w;
            *reinterpret_cast<float4*>(&out[(size_t)rg * 512 + n0 + ocol]) = v;
        }
    }
}

// ---------------------------------------------------------------------------
// Flash attention (FA2, raw mma m16n8k16 bf16 split).
// BM=128 queries/block, 8 warps (16 rows each), BN=64 keys/iter, d=64.
// ---------------------------------------------------------------------------
#define KV_LD 72   // 64 + 8 pad (bf16)

__global__ void __launch_bounds__(256)
attn_tc()
{
    __shared__ __nv_bfloat16 Khi[64][KV_LD], Klo[64][KV_LD];
    __shared__ __nv_bfloat16 Vthi[64][KV_LD], Vtlo[64][KV_LD];  // transposed: [d][key]

    const int tid  = threadIdx.x;
    const int lane = tid & 31;
    const int w    = tid >> 5;       // warp id 0..7
    const int rq   = lane >> 2;      // 0..7
    const int c0   = (lane & 3) * 2; // 0,2,4,6
    const int bh   = blockIdx.y;
    const int m0   = blockIdx.x * 128;

    const float* Qb = g_q + (size_t)bh * NN * DK;
    const float* Kb = g_k + (size_t)bh * NN * DK;
    const float* Vb = g_v + (size_t)bh * NN * DK;

    const float sc = 0.125f * 1.4426950408889634f;  // 1/sqrt(64) * log2(e)

    // persistent Q fragments (scaled, hi/lo split). rows: m0 + w*16 + rq (+8)
    uint32_t qh[4][4], ql[4][4];
    {
        int ra = m0 + w * 16 + rq;
        int rb = ra + 8;
        #pragma unroll
        for (int ks = 0; ks < 4; ks++) {
            int ca = 16 * ks + c0;
            float2 v0 = *reinterpret_cast<const float2*>(&Qb[(size_t)ra * DK + ca]);
            float2 v1 = *reinterpret_cast<const float2*>(&Qb[(size_t)rb * DK + ca]);
            float2 v2 = *reinterpret_cast<const float2*>(&Qb[(size_t)ra * DK + ca + 8]);
            float2 v3 = *reinterpret_cast<const float2*>(&Qb[(size_t)rb * DK + ca + 8]);
            split2(v0.x * sc, v0.y * sc, qh[ks][0], ql[ks][0]);
            split2(v1.x * sc, v1.y * sc, qh[ks][1], ql[ks][1]);
            split2(v2.x * sc, v2.y * sc, qh[ks][2], ql[ks][2]);
            split2(v3.x * sc, v3.y * sc, qh[ks][3], ql[ks][3]);
        }
    }

    float o[8][4];
    #pragma unroll
    for (int j = 0; j < 8; j++)
        #pragma unroll
        for (int e = 0; e < 4; e++) o[j][e] = 0.0f;
    float mrow[2] = {-1e30f, -1e30f};
    float lrow[2] = {0.0f, 0.0f};

    const int ldrow = tid >> 4;          // 0..15
    const int ldcol = (tid & 15) * 4;    // 0..60

    for (int kb = 0; kb < NN; kb += 64) {
        __syncthreads();
        // load K (key-major) and V (transposed, d-major), split hi/lo
        #pragma unroll
        for (int t = 0; t < 4; t++) {
            int r = ldrow + t * 16;     // key index 0..63
            float4 kv = *reinterpret_cast<const float4*>(&Kb[(size_t)(kb + r) * DK + ldcol]);
            uint32_t h01, l01, h23, l23;
            split2(kv.x, kv.y, h01, l01);
            split2(kv.z, kv.w, h23, l23);
            *reinterpret_cast<uint32_t*>(&Khi[r][ldcol])     = h01;
            *reinterpret_cast<uint32_t*>(&Khi[r][ldcol + 2]) = h23;
            *reinterpret_cast<uint32_t*>(&Klo[r][ldcol])     = l01;
            *reinterpret_cast<uint32_t*>(&Klo[r][ldcol + 2]) = l23;

            float4 vv = *reinterpret_cast<const float4*>(&Vb[(size_t)(kb + r) * DK + ldcol]);
            float vh, vl;
            vh = __bfloat162float(__float2bfloat16(vv.x));
            Vthi[ldcol + 0][r] = __float2bfloat16(vh);  Vtlo[ldcol + 0][r] = __float2bfloat16(vv.x - vh);
            vh = __bfloat162float(__float2bfloat16(vv.y));
            Vthi[ldcol + 1][r] = __float2bfloat16(vh);  Vtlo[ldcol + 1][r] = __float2bfloat16(vv.y - vh);
            vh = __bfloat162float(__float2bfloat16(vv.z));
            Vthi[ldcol + 2][r] = __float2bfloat16(vh);  Vtlo[ldcol + 2][r] = __float2bfloat16(vv.z - vh);
            vh = __bfloat162float(__float2bfloat16(vv.w));
            Vthi[ldcol + 3][r] = __float2bfloat16(vh);  Vtlo[ldcol + 3][r] = __float2bfloat16(vv.w - vh);
        }
        __syncthreads();

        // S = Qsc @ K^T  : 8 n-frags (8 keys each), 4 k-steps, 3-way split
        float s[8][4];
        #pragma unroll
        for (int j = 0; j < 8; j++)
            #pragma unroll
            for (int e = 0; e < 4; e++) s[j][e] = 0.0f;

        #pragma unroll
        for (int ks = 0; ks < 4; ks++) {
            int k0 = 16 * ks + c0;
            #pragma unroll
            for (int j = 0; j < 8; j++) {
                int n = 8 * j + rq;
                uint32_t bh0 = *reinterpret_cast<const uint32_t*>(&Khi[n][k0]);
                uint32_t bh1 = *reinterpret_cast<const uint32_t*>(&Khi[n][k0 + 8]);
                uint32_t bl0 = *reinterpret_cast<const uint32_t*>(&Klo[n][k0]);
                uint32_t bl1 = *reinterpret_cast<const uint32_t*>(&Klo[n][k0 + 8]);
                mma16816(s[j], qh[ks], bh0, bh1);
                mma16816(s[j], qh[ks], bl0, bl1);
                mma16816(s[j], ql[ks], bh0, bh1);
            }
        }

        // online softmax per row-half (rows rq / rq+8): elems [2h], [2h+1]
        #pragma unroll
        for (int hh = 0; hh < 2; hh++) {
            float mx = -1e30f;
            #pragma unroll
            for (int j = 0; j < 8; j++)
                mx = fmaxf(mx, fmaxf(s[j][2 * hh], s[j][2 * hh + 1]));
            mx = fmaxf(mx, __shfl_xor_sync(0xffffffffu, mx, 1));
            mx = fmaxf(mx, __shfl_xor_sync(0xffffffffu, mx, 2));
            float mNew = fmaxf(mrow[hh], mx);
            float corr = exp2f(mrow[hh] - mNew);
            float rs = 0.0f;
            #pragma unroll
            for (int j = 0; j < 8; j++) {
                float p0 = exp2f(s[j][2 * hh]     - mNew);
                float p1 = exp2f(s[j][2 * hh + 1] - mNew);
                s[j][2 * hh]     = p0;
                s[j][2 * hh + 1] = p1;
                rs += p0 + p1;
            }
            rs += __shfl_xor_sync(0xffffffffu, rs, 1);
            rs += __shfl_xor_sync(0xffffffffu, rs, 2);
            lrow[hh] = lrow[hh] * corr + rs;
            mrow[hh] = mNew;
            #pragma unroll
            for (int j = 0; j < 8; j++) {
                o[j][2 * hh]     *= corr;
                o[j][2 * hh + 1] *= corr;
            }
        }

        // O += P @ V  (P fragments remapped directly from S accumulators)
        #pragma unroll
        for (int ks = 0; ks < 4; ks++) {
            uint32_t ph[4], pl[4];
            split2(s[2 * ks][0],     s[2 * ks][1],     ph[0], pl[0]);
            split2(s[2 * ks][2],     s[2 * ks][3],     ph[1], pl[1]);
            split2(s[2 * ks + 1][0], s[2 * ks + 1][1], ph[2], pl[2]);
            split2(s[2 * ks + 1][2], s[2 * ks + 1][3], ph[3], pl[3]);
            int k0 = 16 * ks + c0;
            #pragma unroll
            for (int j = 0; j < 8; j++) {
                int n = 8 * j + rq;   // d index
                uint32_t bh0 = *reinterpret_cast<const uint32_t*>(&Vthi[n][k0]);
                uint32_t bh1 = *reinterpret_cast<const uint32_t*>(&Vthi[n][k0 + 8]);
                uint32_t bl0 = *reinterpret_cast<const uint32_t*>(&Vtlo[n][k0]);
                uint32_t bl1 = *reinterpret_cast<const uint32_t*>(&Vtlo[n][k0 + 8]);
                mma16816(o[j], ph, bh0, bh1);
                mma16816(o[j], ph, bl0, bl1);
                mma16816(o[j], pl, bh0, bh1);
            }
        }
    }

    // epilogue: merge heads -> g_attn[b*n][h*64+d]
    const int b_ = bh >> 3;
    const int h  = bh & 7;
    const float i0 = 1.0f / lrow[0];
    const float i1 = 1.0f / lrow[1];
    const int ra = m0 + w * 16 + rq;
    #pragma unroll
    for (int j = 0; j < 8; j++) {
        int col = 8 * j + c0;
        float2 w0 = make_float2(o[j][0] * i0, o[j][1] * i0);
        float2 w1 = make_float2(o[j][2] * i1, o[j][3] * i1);
        size_t off0 = ((size_t)(b_ * NN + ra)) * D_MODEL + h * DK + col;
        size_t off1 = ((size_t)(b_ * NN + ra + 8)) * D_MODEL + h * DK + col;
        *reinterpret_cast<float2*>(&g_attn[off0]) = w0;
        *reinterpret_cast<float2*>(&g_attn[off1]) = w1;
    }
}

// ---------------------------------------------------------------------------
extern "C" void kernel_launch(void* const* d_in, const int* in_sizes, int n_in,
                              void* d_out, int out_size)
{
    (void)in_sizes; (void)n_in; (void)out_size;
    const float* x  = (const float*)d_in[0];
    const float* Wq = (const float*)d_in[1];
    const float* bq = (const float*)d_in[2];
    const float* Wk = (const float*)d_in[3];
    const float* bk = (const float*)d_in[4];
    const float* Wv = (const float*)d_in[5];
    const float* bv = (const float*)d_in[6];
    const float* Wo = (const float*)d_in[7];
    const float* bo = (const float*)d_in[8];

    float *qp, *kp, *vp, *ap;
    cudaGetSymbolAddress((void**)&qp, g_q);
    cudaGetSymbolAddress((void**)&kp, g_k);
    cudaGetSymbolAddress((void**)&vp, g_v);
    cudaGetSymbolAddress((void**)&ap, g_attn);

    dim3 gemm_grid(D_MODEL / 64, M_TOTAL / 128);   // (8, 64)
    gemm_tc<<<gemm_grid, 256>>>(x, Wq, bq, qp, 1);
    gemm_tc<<<gemm_grid, 256>>>(x, Wk, bk, kp, 1);
    gemm_tc<<<gemm_grid, 256>>>(x, Wv, bv, vp, 1);

    dim3 attn_grid(NN / 128, BH);                  // (16, 32)
    attn_tc<<<attn_grid, 256>>>();

    gemm_tc<<<gemm_grid, 256>>>(ap, Wo, bo, (float*)d_out, 0);
}

// round 4
// speedup vs baseline: 2.8488x; 1.3997x over previous
#include <cuda_runtime.h>
#include <cuda_bf16.h>
#include <mma.h>
#include <math.h>
#include <stdint.h>

using namespace nvcuda;

#define D_MODEL 512
#define NHEAD   8
#define DK      64
#define BB      4
#define NN      2048
#define M_TOTAL (BB * NN)     // 8192
#define BH      (BB * NHEAD)  // 32
#define NKV     (NN / 64)     // 32 kv blocks

// Q pre-scale: 1/sqrt(64) * log2(e)
#define SC_ATTN 0.18033688f

// Scratch (allocation-free static __device__ arrays)
__device__ __align__(128) __nv_bfloat16 g_qh[BH * NN * DK];  // [bh][n][d] hi (pre-scaled)
__device__ __align__(128) __nv_bfloat16 g_ql[BH * NN * DK];
__device__ __align__(128) __nv_bfloat16 g_kh[BH * NN * DK];  // [bh][n][d]
__device__ __align__(128) __nv_bfloat16 g_kl[BH * NN * DK];
__device__ __align__(128) __nv_bfloat16 g_vth[BH * DK * NN]; // [bh][d][n] (transposed)
__device__ __align__(128) __nv_bfloat16 g_vtl[BH * DK * NN];
__device__ __align__(128) float g_attn[M_TOTAL * D_MODEL];   // [b*n][512]

// ---------------------------------------------------------------------------
// helpers
// ---------------------------------------------------------------------------
__device__ __forceinline__ uint32_t packb(float x, float y) {
    __nv_bfloat162 t = __floats2bfloat162_rn(x, y);
    return *reinterpret_cast<uint32_t*>(&t);
}
__device__ __forceinline__ void split2(float x, float y, uint32_t& hi, uint32_t& lo) {
    float hx = __bfloat162float(__float2bfloat16(x));
    float hy = __bfloat162float(__float2bfloat16(y));
    hi = packb(hx, hy);
    lo = packb(x - hx, y - hy);
}
__device__ __forceinline__ void mma16816(float* c, const uint32_t* a, uint32_t b0, uint32_t b1) {
    asm volatile(
        "mma.sync.aligned.m16n8k16.row.col.f32.bf16.bf16.f32 "
        "{%0,%1,%2,%3}, {%4,%5,%6,%7}, {%8,%9}, {%0,%1,%2,%3};\n"
        : "+f"(c[0]), "+f"(c[1]), "+f"(c[2]), "+f"(c[3])
        : "r"(a[0]), "r"(a[1]), "r"(a[2]), "r"(a[3]), "r"(b0), "r"(b1));
}
__device__ __forceinline__ void ldsm_x4(uint32_t& d0, uint32_t& d1, uint32_t& d2, uint32_t& d3,
                                        uint32_t saddr) {
    asm volatile("ldmatrix.sync.aligned.m8n8.x4.shared.b16 {%0,%1,%2,%3}, [%4];"
                 : "=r"(d0), "=r"(d1), "=r"(d2), "=r"(d3) : "r"(saddr));
}
__device__ __forceinline__ void cp16(uint32_t dst, const void* src) {
    asm volatile("cp.async.cg.shared.global [%0], [%1], 16;" :: "r"(dst), "l"(src));
}
__device__ __forceinline__ void cp_commit() { asm volatile("cp.async.commit_group;"); }
template<int N> __device__ __forceinline__ void cp_wait() {
    asm volatile("cp.async.wait_group %0;" :: "n"(N));
}
// swizzled byte offset inside a tile of 128-byte rows (8 x 16B chunks)
__device__ __forceinline__ uint32_t SW(uint32_t r, uint32_t c) {
    return r * 128u + ((c ^ (r & 7u)) << 4);
}

// ---------------------------------------------------------------------------
// GEMM (tensor core, split bf16): out = X[M,512] @ W[512,512] + bias
// 128x64 tile, BK=32, 256 thr, 8 warps. Epilogue modes:
//   0: fp32 out [row][512]
//   1: split bf16 [bh][n][64] (scale applied)  (Q,K)
//   2: split bf16 transposed [bh][d][n]        (V)
// ---------------------------------------------------------------------------
#define XS_LD 40
#define WS_LD 72
#define CS_LD 68

__global__ void __launch_bounds__(256)
gemm_tc(const float* __restrict__ X, const float* __restrict__ W,
        const float* __restrict__ bias, void* __restrict__ out0,
        void* __restrict__ out1, int mode, float scale)
{
    __shared__ __align__(16) unsigned char smem_raw[128 * CS_LD * 4];
    __nv_bfloat16* Xhi = (__nv_bfloat16*)smem_raw;
    __nv_bfloat16* Xlo = Xhi + 128 * XS_LD;
    __nv_bfloat16* Whi = Xlo + 128 * XS_LD;
    __nv_bfloat16* Wlo = Whi + 32 * WS_LD;
    float* Cst = (float*)smem_raw;

    const int tid = threadIdx.x;
    const int wid = tid >> 5;
    const int wm  = wid & 3;
    const int wn  = wid >> 2;
    const int m0  = blockIdx.y * 128;
    const int n0  = blockIdx.x * 64;

    wmma::fragment<wmma::accumulator, 16, 16, 16, float> acc[2][2];
    #pragma unroll
    for (int i = 0; i < 2; i++)
        #pragma unroll
        for (int j = 0; j < 2; j++)
            wmma::fill_fragment(acc[i][j], 0.0f);

    const int xrow = tid >> 3;
    const int xcol = (tid & 7) * 4;
    const int wrow = tid >> 4;
    const int wcol = (tid & 15) * 4;

    for (int kt = 0; kt < 512; kt += 32) {
        #pragma unroll
        for (int t = 0; t < 4; t++) {
            int r = xrow + t * 32;
            float4 v = *reinterpret_cast<const float4*>(&X[(size_t)(m0 + r) * 512 + kt + xcol]);
            uint32_t h01, l01, h23, l23;
            split2(v.x, v.y, h01, l01);
            split2(v.z, v.w, h23, l23);
            *reinterpret_cast<uint32_t*>(&Xhi[r * XS_LD + xcol])     = h01;
            *reinterpret_cast<uint32_t*>(&Xhi[r * XS_LD + xcol + 2]) = h23;
            *reinterpret_cast<uint32_t*>(&Xlo[r * XS_LD + xcol])     = l01;
            *reinterpret_cast<uint32_t*>(&Xlo[r * XS_LD + xcol + 2]) = l23;
        }
        #pragma unroll
        for (int t = 0; t < 2; t++) {
            int r = wrow + t * 16;
            float4 v = *reinterpret_cast<const float4*>(&W[(size_t)(kt + r) * 512 + n0 + wcol]);
            uint32_t h01, l01, h23, l23;
            split2(v.x, v.y, h01, l01);
            split2(v.z, v.w, h23, l23);
            *reinterpret_cast<uint32_t*>(&Whi[r * WS_LD + wcol])     = h01;
            *reinterpret_cast<uint32_t*>(&Whi[r * WS_LD + wcol + 2]) = h23;
            *reinterpret_cast<uint32_t*>(&Wlo[r * WS_LD + wcol])     = l01;
            *reinterpret_cast<uint32_t*>(&Wlo[r * WS_LD + wcol + 2]) = l23;
        }
        __syncthreads();

        #pragma unroll
        for (int kk = 0; kk < 32; kk += 16) {
            wmma::fragment<wmma::matrix_a, 16, 16, 16, __nv_bfloat16, wmma::row_major> ahi[2], alo[2];
            #pragma unroll
            for (int i = 0; i < 2; i++) {
                wmma::load_matrix_sync(ahi[i], Xhi + (wm * 32 + 16 * i) * XS_LD + kk, XS_LD);
                wmma::load_matrix_sync(alo[i], Xlo + (wm * 32 + 16 * i) * XS_LD + kk, XS_LD);
            }
            #pragma unroll
            for (int j = 0; j < 2; j++) {
                wmma::fragment<wmma::matrix_b, 16, 16, 16, __nv_bfloat16, wmma::row_major> bhi, blo;
                wmma::load_matrix_sync(bhi, Whi + kk * WS_LD + wn * 32 + 16 * j, WS_LD);
                wmma::load_matrix_sync(blo, Wlo + kk * WS_LD + wn * 32 + 16 * j, WS_LD);
                #pragma unroll
                for (int i = 0; i < 2; i++) {
                    wmma::mma_sync(acc[i][j], ahi[i], bhi, acc[i][j]);
                    wmma::mma_sync(acc[i][j], ahi[i], blo, acc[i][j]);
                    wmma::mma_sync(acc[i][j], alo[i], bhi, acc[i][j]);
                }
            }
        }
        __syncthreads();
    }

    #pragma unroll
    for (int i = 0; i < 2; i++)
        #pragma unroll
        for (int j = 0; j < 2; j++)
            wmma::store_matrix_sync(Cst + (wm * 32 + 16 * i) * CS_LD + wn * 32 + 16 * j,
                                    acc[i][j], CS_LD, wmma::mem_row_major);
    __syncthreads();

    if (mode == 0) {
        float* out = (float*)out0;
        const int orow = tid >> 4;
        const int ocol = (tid & 15) * 4;
        float4 b4 = *reinterpret_cast<const float4*>(&bias[n0 + ocol]);
        #pragma unroll
        for (int t = 0; t < 8; t++) {
            int r = orow + t * 16;
            float4 v = *reinterpret_cast<const float4*>(&Cst[r * CS_LD + ocol]);
            v.x += b4.x; v.y += b4.y; v.z += b4.z; v.w += b4.w;
            *reinterpret_cast<float4*>(&out[(size_t)(m0 + r) * 512 + n0 + ocol]) = v;
        }
    } else if (mode == 1) {
        __nv_bfloat16* ohi = (__nv_bfloat16*)out0;
        __nv_bfloat16* olo = (__nv_bfloat16*)out1;
        const int h = blockIdx.x;           // n0 = h*64
        const int orow = tid >> 4;
        const int ocol = (tid & 15) * 4;    // d within head
        float4 b4 = *reinterpret_cast<const float4*>(&bias[n0 + ocol]);
        #pragma unroll
        for (int t = 0; t < 8; t++) {
            int r  = orow + t * 16;
            int rg = m0 + r;
            int b_ = rg >> 11;
            int n_ = rg & 2047;
            float4 v = *reinterpret_cast<const float4*>(&Cst[r * CS_LD + ocol]);
            float v0 = (v.x + b4.x) * scale;
            float v1 = (v.y + b4.y) * scale;
            float v2 = (v.z + b4.z) * scale;
            float v3 = (v.w + b4.w) * scale;
            uint32_t h01, l01, h23, l23;
            split2(v0, v1, h01, l01);
            split2(v2, v3, h23, l23);
            size_t off = ((size_t)(b_ * NHEAD + h) * NN + n_) * DK + ocol;
            *reinterpret_cast<uint2*>(&ohi[off]) = make_uint2(h01, h23);
            *reinterpret_cast<uint2*>(&olo[off]) = make_uint2(l01, l23);
        }
    } else {
        // mode 2: V transposed [bh][d][n]
        __nv_bfloat16* ohi = (__nv_bfloat16*)out0;
        __nv_bfloat16* olo = (__nv_bfloat16*)out1;
        const int h   = blockIdx.x;
        const int od  = tid >> 2;           // 0..63 d index
        const int on0 = (tid & 3) * 32;
        const int b_  = m0 >> 11;
        const int nb  = (m0 & 2047) + on0;
        const float bv = bias[n0 + od];
        size_t rowoff = ((size_t)(b_ * NHEAD + h) * DK + od) * NN + nb;
        #pragma unroll
        for (int i = 0; i < 32; i += 2) {
            float v0 = Cst[(on0 + i) * CS_LD + od] + bv;
            float v1 = Cst[(on0 + i + 1) * CS_LD + od] + bv;
            uint32_t hp, lp;
            split2(v0, v1, hp, lp);
            *reinterpret_cast<uint32_t*>(&ohi[rowoff + i]) = hp;
            *reinterpret_cast<uint32_t*>(&olo[rowoff + i]) = lp;
        }
    }
}

// ---------------------------------------------------------------------------
// Flash attention: BM=128, BN=64, d=64, 256 thr / 8 warps, 2 CTAs/SM.
// Q in smem (ldmatrix), K/V double-buffered via cp.async, split-bf16 mma.
// Dynamic smem layout (bytes):
//   Qhi 0..16K, Qlo 16K..32K
//   buf b at 32K + 32K*b: Khi(8K), Klo(8K), Vthi(8K), Vtlo(8K)
// ---------------------------------------------------------------------------
#define SM_QHI 0
#define SM_QLO 16384
#define SM_BUF(b) (32768 + (b) * 32768)
#define SM_KHI 0
#define SM_KLO 8192
#define SM_VHI 16384
#define SM_VLO 24576
#define ATTN_SMEM (32768 + 2 * 32768)   // 96 KB

__global__ void __launch_bounds__(256, 2)
attn_tc()
{
    extern __shared__ __align__(128) unsigned char sm[];
    const uint32_t sbase = (uint32_t)__cvta_generic_to_shared(sm);

    const int tid  = threadIdx.x;
    const int lane = tid & 31;
    const int w    = tid >> 5;
    const int rq   = lane >> 2;
    const int bh   = blockIdx.y;
    const int m0   = blockIdx.x * 128;

    const __nv_bfloat16* qh_g = g_qh + (size_t)bh * NN * DK;
    const __nv_bfloat16* ql_g = g_ql + (size_t)bh * NN * DK;
    const __nv_bfloat16* kh_g = g_kh + (size_t)bh * NN * DK;
    const __nv_bfloat16* kl_g = g_kl + (size_t)bh * NN * DK;
    const __nv_bfloat16* vh_g = g_vth + (size_t)bh * DK * NN;
    const __nv_bfloat16* vl_g = g_vtl + (size_t)bh * DK * NN;

    // ---- load Q tile (rows m0..m0+127) into smem, swizzled ----
    {
        #pragma unroll
        for (int p = 0; p < 4; p++) {
            int id = tid + p * 256;          // 0..1023
            int r = id >> 3, c = id & 7;
            size_t go = (size_t)(m0 + r) * DK + c * 8;
            uint32_t so = SW(r, c);
            cp16(sbase + SM_QHI + so, qh_g + go);
            cp16(sbase + SM_QLO + so, ql_g + go);
        }
        cp_commit();
    }
    // ---- KV block 0 into buf 0 ----
    {
        #pragma unroll
        for (int p = 0; p < 2; p++) {
            int id = tid + p * 256;          // 0..511
            int r = id >> 3, c = id & 7;
            uint32_t so = SW(r, c);
            size_t ko = (size_t)r * DK + c * 8;
            size_t vo = (size_t)r * NN + c * 8;
            cp16(sbase + SM_BUF(0) + SM_KHI + so, kh_g + ko);
            cp16(sbase + SM_BUF(0) + SM_KLO + so, kl_g + ko);
            cp16(sbase + SM_BUF(0) + SM_VHI + so, vh_g + vo);
            cp16(sbase + SM_BUF(0) + SM_VLO + so, vl_g + vo);
        }
        cp_commit();
    }

    float o[8][4];
    #pragma unroll
    for (int j = 0; j < 8; j++)
        #pragma unroll
        for (int e = 0; e < 4; e++) o[j][e] = 0.0f;
    float mrow[2] = {-1e30f, -1e30f};
    float lrow[2] = {0.0f, 0.0f};

    // per-thread ldmatrix lane geometry
    const uint32_t qrow = w * 16 + (lane & 15);
    const uint32_t qc   = lane >> 4;                       // 0/1 -> k chunk half
    const uint32_t qoff = qrow * 128;
    const uint32_t qxr  = qrow & 7;
    const uint32_t brow = ((lane >> 4) << 3) + (lane & 7); // 0..15
    const uint32_t bc   = (lane >> 3) & 1;
    const uint32_t bxr  = brow & 7;

    for (int i = 0; i < NKV; i++) {
        // prefetch next KV block
        if (i < NKV - 1) {
            int buf = (i + 1) & 1;
            int kb = (i + 1) * 64;
            #pragma unroll
            for (int p = 0; p < 2; p++) {
                int id = tid + p * 256;
                int r = id >> 3, c = id & 7;
                uint32_t so = SW(r, c);
                size_t ko = (size_t)(kb + r) * DK + c * 8;
                size_t vo = (size_t)r * NN + kb + c * 8;
                cp16(sbase + SM_BUF(buf) + SM_KHI + so, kh_g + ko);
                cp16(sbase + SM_BUF(buf) + SM_KLO + so, kl_g + ko);
                cp16(sbase + SM_BUF(buf) + SM_VHI + so, vh_g + vo);
                cp16(sbase + SM_BUF(buf) + SM_VLO + so, vl_g + vo);
            }
            cp_commit();
            cp_wait<1>();
        } else {
            cp_wait<0>();
        }
        __syncthreads();

        const uint32_t kbuf = sbase + SM_BUF(i & 1);

        // ---- S = Q @ K^T ----
        float s[8][4];
        #pragma unroll
        for (int j = 0; j < 8; j++)
            #pragma unroll
            for (int e = 0; e < 4; e++) s[j][e] = 0.0f;

        #pragma unroll
        for (int ks = 0; ks < 4; ks++) {
            uint32_t qh[4], ql[4];
            uint32_t qcc = 2 * ks + qc;
            ldsm_x4(qh[0], qh[1], qh[2], qh[3], sbase + SM_QHI + qoff + (((qcc ^ qxr)) << 4));
            ldsm_x4(ql[0], ql[1], ql[2], ql[3], sbase + SM_QLO + qoff + (((qcc ^ qxr)) << 4));
            uint32_t bcc = 2 * ks + bc;
            #pragma unroll
            for (int jp = 0; jp < 4; jp++) {
                uint32_t row = 16 * jp + brow;
                uint32_t off = row * 128 + ((bcc ^ bxr) << 4);
                uint32_t kh0, kh1, kh2, kh3, kl0, kl1, kl2, kl3;
                ldsm_x4(kh0, kh1, kh2, kh3, kbuf + SM_KHI + off);
                ldsm_x4(kl0, kl1, kl2, kl3, kbuf + SM_KLO + off);
                mma16816(s[2 * jp],     qh, kh0, kh1);
                mma16816(s[2 * jp],     qh, kl0, kl1);
                mma16816(s[2 * jp],     ql, kh0, kh1);
                mma16816(s[2 * jp + 1], qh, kh2, kh3);
                mma16816(s[2 * jp + 1], qh, kl2, kl3);
                mma16816(s[2 * jp + 1], ql, kh2, kh3);
            }
        }

        // ---- online softmax (logits already in log2 units) ----
        #pragma unroll
        for (int hh = 0; hh < 2; hh++) {
            float mx = -1e30f;
            #pragma unroll
            for (int j = 0; j < 8; j++)
                mx = fmaxf(mx, fmaxf(s[j][2 * hh], s[j][2 * hh + 1]));
            mx = fmaxf(mx, __shfl_xor_sync(0xffffffffu, mx, 1));
            mx = fmaxf(mx, __shfl_xor_sync(0xffffffffu, mx, 2));
            float mNew = fmaxf(mrow[hh], mx);
            float corr = exp2f(mrow[hh] - mNew);
            float rs = 0.0f;
            #pragma unroll
            for (int j = 0; j < 8; j++) {
                float p0 = exp2f(s[j][2 * hh]     - mNew);
                float p1 = exp2f(s[j][2 * hh + 1] - mNew);
                s[j][2 * hh]     = p0;
                s[j][2 * hh + 1] = p1;
                rs += p0 + p1;
            }
            rs += __shfl_xor_sync(0xffffffffu, rs, 1);
            rs += __shfl_xor_sync(0xffffffffu, rs, 2);
            lrow[hh] = lrow[hh] * corr + rs;
            mrow[hh] = mNew;
            #pragma unroll
            for (int j = 0; j < 8; j++) {
                o[j][2 * hh]     *= corr;
                o[j][2 * hh + 1] *= corr;
            }
        }

        // ---- O += P @ V ----
        #pragma unroll
        for (int ks = 0; ks < 4; ks++) {
            uint32_t ph[4], pl[4];
            split2(s[2 * ks][0],     s[2 * ks][1],     ph[0], pl[0]);
            split2(s[2 * ks][2],     s[2 * ks][3],     ph[1], pl[1]);
            split2(s[2 * ks + 1][0], s[2 * ks + 1][1], ph[2], pl[2]);
            split2(s[2 * ks + 1][2], s[2 * ks + 1][3], ph[3], pl[3]);
            uint32_t bcc = 2 * ks + bc;
            #pragma unroll
            for (int jp = 0; jp < 4; jp++) {
                uint32_t row = 16 * jp + brow;
                uint32_t off = row * 128 + ((bcc ^ bxr) << 4);
                uint32_t vh0, vh1, vh2, vh3, vl0, vl1, vl2, vl3;
                ldsm_x4(vh0, vh1, vh2, vh3, kbuf + SM_VHI + off);
                ldsm_x4(vl0, vl1, vl2, vl3, kbuf + SM_VLO + off);
                mma16816(o[2 * jp],     ph, vh0, vh1);
                mma16816(o[2 * jp],     ph, vl0, vl1);
                mma16816(o[2 * jp],     pl, vh0, vh1);
                mma16816(o[2 * jp + 1], ph, vh2, vh3);
                mma16816(o[2 * jp + 1], ph, vl2, vl3);
                mma16816(o[2 * jp + 1], pl, vh2, vh3);
            }
        }
        __syncthreads();
    }

    // epilogue: merge heads -> g_attn[b*n][h*64+d]
    const int b_ = bh >> 3;
    const int h  = bh & 7;
    const int c0 = (lane & 3) * 2;
    const float i0 = 1.0f / lrow[0];
    const float i1 = 1.0f / lrow[1];
    const int ra = m0 + w * 16 + rq;
    #pragma unroll
    for (int j = 0; j < 8; j++) {
        int col = 8 * j + c0;
        float2 w0 = make_float2(o[j][0] * i0, o[j][1] * i0);
        float2 w1 = make_float2(o[j][2] * i1, o[j][3] * i1);
        size_t off0 = ((size_t)(b_ * NN + ra)) * D_MODEL + h * DK + col;
        size_t off1 = ((size_t)(b_ * NN + ra + 8)) * D_MODEL + h * DK + col;
        *reinterpret_cast<float2*>(&g_attn[off0]) = w0;
        *reinterpret_cast<float2*>(&g_attn[off1]) = w1;
    }
}

// ---------------------------------------------------------------------------
extern "C" void kernel_launch(void* const* d_in, const int* in_sizes, int n_in,
                              void* d_out, int out_size)
{
    (void)in_sizes; (void)n_in; (void)out_size;
    const float* x  = (const float*)d_in[0];
    const float* Wq = (const float*)d_in[1];
    const float* bq = (const float*)d_in[2];
    const float* Wk = (const float*)d_in[3];
    const float* bk = (const float*)d_in[4];
    const float* Wv = (const float*)d_in[5];
    const float* bv = (const float*)d_in[6];
    const float* Wo = (const float*)d_in[7];
    const float* bo = (const float*)d_in[8];

    void *qh, *ql, *kh, *kl, *vh, *vl, *ap;
    cudaGetSymbolAddress(&qh, g_qh);
    cudaGetSymbolAddress(&ql, g_ql);
    cudaGetSymbolAddress(&kh, g_kh);
    cudaGetSymbolAddress(&kl, g_kl);
    cudaGetSymbolAddress(&vh, g_vth);
    cudaGetSymbolAddress(&vl, g_vtl);
    cudaGetSymbolAddress(&ap, g_attn);

    cudaFuncSetAttribute(attn_tc, cudaFuncAttributeMaxDynamicSharedMemorySize, ATTN_SMEM);

    dim3 gemm_grid(D_MODEL / 64, M_TOTAL / 128);   // (8, 64)
    gemm_tc<<<gemm_grid, 256>>>(x, Wq, bq, qh, ql, 1, SC_ATTN);
    gemm_tc<<<gemm_grid, 256>>>(x, Wk, bk, kh, kl, 1, 1.0f);
    gemm_tc<<<gemm_grid, 256>>>(x, Wv, bv, vh, vl, 2, 1.0f);

    dim3 attn_grid(NN / 128, BH);                  // (16, 32)
    attn_tc<<<attn_grid, 256, ATTN_SMEM>>>();

    gemm_tc<<<gemm_grid, 256>>>((const float*)ap, Wo, bo, d_out, nullptr, 0, 1.0f);
}